// round 1
// baseline (speedup 1.0000x reference)
#include <cuda_runtime.h>
#include <math.h>

#define BATCH   128
#define SEQ     512
#define INPUT   512
#define HIDDEN  1024
#define OUTPUT  256
#define NBLK    128

// Scratch (device globals: no allocation allowed)
__device__ float g_xin[(size_t)SEQ * BATCH * HIDDEN];   // [s][b][h] time-major for scan reads
__device__ float g_h[2][BATCH * HIDDEN];                // ping-pong hidden state
__device__ unsigned g_bar_cnt;
__device__ unsigned g_bar_gen;

// ---------------------------------------------------------------------------
// Device-wide barrier (all NBLK blocks resident; NBLK <= 148 SMs guarantees it)
// ---------------------------------------------------------------------------
__device__ __forceinline__ void grid_sync(unsigned target)
{
    __threadfence();           // make this thread's global writes visible
    __syncthreads();
    if (threadIdx.x == 0) {
        unsigned arrived = atomicAdd(&g_bar_cnt, 1u);
        if (arrived == NBLK - 1) {
            atomicExch(&g_bar_cnt, 0u);
            __threadfence();
            atomicAdd(&g_bar_gen, 1u);
        } else {
            while (*(volatile unsigned*)&g_bar_gen != target) { }
            __threadfence();
        }
    }
    __syncthreads();
}

// ---------------------------------------------------------------------------
// Phase 1: xin[s][b][n] = x[b][s][:] @ W_in[:, n] + b_in[n]
// Tiled fp32 GEMM: BM=64, BN=64, BK=16, 256 threads, 4x4 per thread.
// ---------------------------------------------------------------------------
__global__ __launch_bounds__(256) void gemm_xin_kernel(
    const float* __restrict__ x,
    const float* __restrict__ Win,
    const float* __restrict__ bin)
{
    __shared__ float As[16][64];   // [k][m]
    __shared__ float Bs[16][64];   // [k][n]

    const int tid = threadIdx.x;
    const int m0 = blockIdx.y * 64;
    const int n0 = blockIdx.x * 64;
    const int ty = tid >> 4;       // 0..15
    const int tx = tid & 15;       // 0..15

    float acc[4][4];
#pragma unroll
    for (int i = 0; i < 4; ++i)
#pragma unroll
        for (int j = 0; j < 4; ++j) acc[i][j] = 0.0f;

    const int arow = tid >> 2;     // 0..63
    const int akq  = tid & 3;      // 0..3  (k float4)
    const int brow = tid >> 4;     // 0..15 (k)
    const int bnq  = tid & 15;     // 0..15 (n float4)

    for (int k0 = 0; k0 < INPUT; k0 += 16) {
        float4 av = *(const float4*)(x   + (size_t)(m0 + arow) * INPUT  + k0 + akq * 4);
        float4 bv = *(const float4*)(Win + (size_t)(k0 + brow) * HIDDEN + n0 + bnq * 4);
        __syncthreads();
        As[akq * 4 + 0][arow] = av.x;
        As[akq * 4 + 1][arow] = av.y;
        As[akq * 4 + 2][arow] = av.z;
        As[akq * 4 + 3][arow] = av.w;
        *(float4*)&Bs[brow][bnq * 4] = bv;
        __syncthreads();
#pragma unroll
        for (int kk = 0; kk < 16; ++kk) {
            float4 a4 = *(const float4*)&As[kk][ty * 4];
            float4 b4 = *(const float4*)&Bs[kk][tx * 4];
            float a[4] = {a4.x, a4.y, a4.z, a4.w};
            float b[4] = {b4.x, b4.y, b4.z, b4.w};
#pragma unroll
            for (int i = 0; i < 4; ++i)
#pragma unroll
                for (int j = 0; j < 4; ++j)
                    acc[i][j] += a[i] * b[j];
        }
    }

    float4 bi = *(const float4*)(bin + n0 + tx * 4);
#pragma unroll
    for (int i = 0; i < 4; ++i) {
        int m = m0 + ty * 4 + i;
        int b = m >> 9;          // batch
        int s = m & 511;         // seq
        float4 r;
        r.x = acc[i][0] + bi.x;
        r.y = acc[i][1] + bi.y;
        r.z = acc[i][2] + bi.z;
        r.w = acc[i][3] + bi.w;
        *(float4*)(g_xin + ((size_t)s * BATCH + b) * HIDDEN + n0 + tx * 4) = r;
    }
}

// ---------------------------------------------------------------------------
// Phase 2+3: persistent scan kernel. 128 blocks = 8 batch-tiles x 16 j-tiles.
// Each step: z = xin_t + h_old @ W_h + b_h ; dx = tanh(z) ;
//            h_new = h_old + (dx - h_old) / tau ; grid barrier ; swap.
// Then out = h_final @ W_out + b_out (blocks 0..63).
// ---------------------------------------------------------------------------
#define SCAN_SMEM_FLOATS (16 * 1024 + 2 * 16 * 64 + 64 + 64)
#define SCAN_SMEM_BYTES  (SCAN_SMEM_FLOATS * 4)

__global__ __launch_bounds__(256, 1) void scan_kernel(
    const float* __restrict__ Wh,
    const float* __restrict__ bh,
    const float* __restrict__ tau,
    const float* __restrict__ Wout,
    const float* __restrict__ bout,
    float* __restrict__ out)
{
    extern __shared__ float smem[];
    float* h_s    = smem;              // [16][1024]  64 KB
    float* ws     = smem + 16 * 1024;  // [2][16][64]  8 KB (double-buffered W chunk)
    float* bh_s   = ws + 2048;         // [64]
    float* itau_s = bh_s + 64;         // [64]

    const int tid = threadIdx.x;
    const int bt  = blockIdx.x >> 4;   // 0..7  batch tile
    const int jt  = blockIdx.x & 15;   // 0..15 hidden tile
    const int b0  = bt * 16;
    const int j0  = jt * 64;
    const int ty  = tid >> 4;          // batch row 0..15
    const int tx  = tid & 15;          // j quad  0..15

    __shared__ unsigned sh_gen0;
    if (tid == 0) sh_gen0 = *(volatile unsigned*)&g_bar_gen;
    if (tid < 64) {
        bh_s[tid]   = bh[j0 + tid];
        itau_s[tid] = 1.0f / tau[j0 + tid];
    }
    // zero h0 (this block's [16 x 64] slice)
    {
        float4 z = make_float4(0.f, 0.f, 0.f, 0.f);
        *(float4*)(&g_h[0][(size_t)(b0 + ty) * HIDDEN + j0 + tx * 4]) = z;
    }
    __syncthreads();

    unsigned nbar = 0;
    grid_sync(sh_gen0 + (++nbar));

    const int wr = tid >> 4;   // W chunk row 0..15
    const int wc = tid & 15;   // W chunk col quad

    int cur = 0;
    for (int t = 0; t < SEQ; ++t) {
        const float* hsrc = g_h[cur];
        // Stage h_old [16 x 1024] into smem (L2-coherent loads; L1 may be stale)
        for (int q = tid; q < 16 * 256; q += 256) {
            int r = q >> 8;      // 0..15
            int c = q & 255;     // float4 index
            float4 v = __ldcg((const float4*)(hsrc + (size_t)(b0 + r) * HIDDEN) + c);
            *(float4*)&h_s[r * HIDDEN + c * 4] = v;
        }

        // acc = xin_t + b_h
        float4 acc = *(const float4*)(g_xin + ((size_t)t * BATCH + (b0 + ty)) * HIDDEN + j0 + tx * 4);
        acc.x += bh_s[tx * 4 + 0];
        acc.y += bh_s[tx * 4 + 1];
        acc.z += bh_s[tx * 4 + 2];
        acc.w += bh_s[tx * 4 + 3];

        // Preload W chunk 0
        float4 wv = *(const float4*)(Wh + (size_t)wr * HIDDEN + j0 + wc * 4);
        __syncthreads();                 // h_s fully staged, ws free
        *(float4*)&ws[0 * 1024 + wr * 64 + wc * 4] = wv;
        __syncthreads();

        for (int c = 0; c < 64; ++c) {
            if (c + 1 < 64)
                wv = *(const float4*)(Wh + (size_t)(16 * (c + 1) + wr) * HIDDEN + j0 + wc * 4);

            const float* hp = &h_s[ty * HIDDEN + c * 16];
            const float* wb = &ws[(c & 1) * 1024];
#pragma unroll
            for (int g = 0; g < 4; ++g) {
                float4 hg = *(const float4*)(hp + g * 4);
                float hx[4] = {hg.x, hg.y, hg.z, hg.w};
#pragma unroll
                for (int kk = 0; kk < 4; ++kk) {
                    float4 w = *(const float4*)&wb[(g * 4 + kk) * 64 + tx * 4];
                    float hv = hx[kk];
                    acc.x += hv * w.x;
                    acc.y += hv * w.y;
                    acc.z += hv * w.z;
                    acc.w += hv * w.w;
                }
            }
            if (c + 1 < 64)
                *(float4*)&ws[((c + 1) & 1) * 1024 + wr * 64 + wc * 4] = wv;
            __syncthreads();
        }

        // h update
        float4 hold = *(const float4*)&h_s[ty * HIDDEN + j0 + tx * 4];
        float4 dx;
        dx.x = tanhf(acc.x);
        dx.y = tanhf(acc.y);
        dx.z = tanhf(acc.z);
        dx.w = tanhf(acc.w);
        float4 hn;
        hn.x = hold.x + (dx.x - hold.x) * itau_s[tx * 4 + 0];
        hn.y = hold.y + (dx.y - hold.y) * itau_s[tx * 4 + 1];
        hn.z = hold.z + (dx.z - hold.z) * itau_s[tx * 4 + 2];
        hn.w = hold.w + (dx.w - hold.w) * itau_s[tx * 4 + 3];
        *(float4*)(g_h[cur ^ 1] + (size_t)(b0 + ty) * HIDDEN + j0 + tx * 4) = hn;

        grid_sync(sh_gen0 + (++nbar));
        cur ^= 1;
    }
    // cur == 0 after 512 flips; h_final = g_h[0]

    // ---------------- Phase 3: out = h_final @ W_out + b_out -----------------
    if (blockIdx.x < 64) {
        const int bt3 = blockIdx.x >> 3;   // 0..7
        const int ot  = blockIdx.x & 7;    // 0..7
        const int b03 = bt3 * 16;
        const int o0  = ot * 32;

        for (int q = tid; q < 16 * 256; q += 256) {
            int r = q >> 8, cq = q & 255;
            float4 v = __ldcg((const float4*)(g_h[cur] + (size_t)(b03 + r) * HIDDEN) + cq);
            *(float4*)&h_s[r * HIDDEN + cq * 4] = v;
        }
        __syncthreads();

        float a0 = bout[o0 + tx];
        float a1 = bout[o0 + tx + 16];
        float* wo_s = ws;   // reuse: [64][32] = 2048 floats

        for (int kc = 0; kc < HIDDEN; kc += 64) {
            __syncthreads();
#pragma unroll
            for (int u = 0; u < 2; ++u) {
                int idx = tid * 2 + u;       // 0..511 float4s
                int r = idx >> 3, c4 = idx & 7;
                *(float4*)&wo_s[r * 32 + c4 * 4] =
                    *(const float4*)(Wout + (size_t)(kc + r) * OUTPUT + o0 + c4 * 4);
            }
            __syncthreads();
#pragma unroll 16
            for (int kk = 0; kk < 64; ++kk) {
                float hv = h_s[ty * HIDDEN + kc + kk];
                a0 += hv * wo_s[kk * 32 + tx];
                a1 += hv * wo_s[kk * 32 + tx + 16];
            }
        }
        out[(size_t)(b03 + ty) * OUTPUT + o0 + tx]      = a0;
        out[(size_t)(b03 + ty) * OUTPUT + o0 + tx + 16] = a1;
    }
}

// ---------------------------------------------------------------------------
// Launch
// Inputs (metadata order): x, W_in, b_in, W_h, b_h, tau, W_out, b_out
// ---------------------------------------------------------------------------
extern "C" void kernel_launch(void* const* d_in, const int* in_sizes, int n_in,
                              void* d_out, int out_size)
{
    const float* x    = (const float*)d_in[0];
    const float* Win  = (const float*)d_in[1];
    const float* bin  = (const float*)d_in[2];
    const float* Wh   = (const float*)d_in[3];
    const float* bhp  = (const float*)d_in[4];
    const float* tau  = (const float*)d_in[5];
    const float* Wout = (const float*)d_in[6];
    const float* bout = (const float*)d_in[7];
    float* out = (float*)d_out;

    cudaFuncSetAttribute(scan_kernel, cudaFuncAttributeMaxDynamicSharedMemorySize,
                         SCAN_SMEM_BYTES);

    dim3 grid1(HIDDEN / 64, (BATCH * SEQ) / 64);   // 16 x 1024
    gemm_xin_kernel<<<grid1, 256>>>(x, Win, bin);

    scan_kernel<<<NBLK, 256, SCAN_SMEM_BYTES>>>(Wh, bhp, tau, Wout, bout, out);
}